// round 16
// baseline (speedup 1.0000x reference)
#include <cuda_runtime.h>
#include <cuda_fp16.h>
#include <math.h>
#include <stdint.h>

// LSTMCell fused, fp16 mma.sync.m16n8k16 f32-accum (sm_103 — no tcgen05 in toolchain).
// Main GEMM kernel sits at the legacy-HMMA issue wall (~877us = 67.1M HMMA at
// ~16 cyc/SMSP cadence). This round: cvt pre-pass keeps fp16 scratch in L2
// (default stores; __ldcs only for read-once fp32 sources) + more threads;
// main loop hoists per-slot smem base addresses. Main kernel otherwise frozen.
// CTA tile 128(M) x 128(N = 4 gates x 32 h); 256 threads, 8 warps (2M x 4N),
// warp tile 64x32, K=2048 in 32 stages of 64 halves, 3-slot cp.async pipeline,
// 2 CTAs/SM, fused LSTM epilogue via smem transpose.

#define Bsz 16384
#define Hd  1024
#define BKH 64                     // halves per K stage
#define SROW 72                    // 64 + 8 pad halves (144B rows, LDSM conflict-free)
#define A_STAGE_H (128 * SROW)     // 9216 halves
#define B_STAGE_H (128 * SROW)     // 9216 halves
#define STAGE_H   (A_STAGE_H + B_STAGE_H)
#define STAGE_BYTES (STAGE_H * 2)  // 36864 B
#define NSTAGE 3

__device__ __half g_xh[33554432];  // x | h   (2 x 16M)
__device__ __half g_ww[8388608];   // Wi | Wh (2 x 4M)

// Streaming conversion: read-once fp32 via __ldcs; fp16 scratch written with
// default (write-back) stores so it stays resident in L2 for the main kernel.
__global__ __launch_bounds__(512) void cvt_all_kernel(
    const float* __restrict__ x,  const float* __restrict__ h,
    const float* __restrict__ Wi, const float* __restrict__ Wh)
{
    const int nthreads = gridDim.x * blockDim.x;
    // 41943040 floats / 16 = 2621440 iterations
    for (int i = blockIdx.x * blockDim.x + threadIdx.x; i < 2621440; i += nthreads) {
        const float* src; __half* dst; int off;   // off in 16-float units
        if (i < 1048576)      { src = x;  dst = g_xh;            off = i; }
        else if (i < 2097152) { src = h;  dst = g_xh + 16777216; off = i - 1048576; }
        else if (i < 2359296) { src = Wi; dst = g_ww;            off = i - 2097152; }
        else                  { src = Wh; dst = g_ww + 4194304;  off = i - 2359296; }
        const float4* s4 = reinterpret_cast<const float4*>(src) + off * 4;
        float4 v0 = __ldcs(s4);
        float4 v1 = __ldcs(s4 + 1);
        float4 v2 = __ldcs(s4 + 2);
        float4 v3 = __ldcs(s4 + 3);
        __half2 hh[8];
        hh[0] = __floats2half2_rn(v0.x, v0.y);
        hh[1] = __floats2half2_rn(v0.z, v0.w);
        hh[2] = __floats2half2_rn(v1.x, v1.y);
        hh[3] = __floats2half2_rn(v1.z, v1.w);
        hh[4] = __floats2half2_rn(v2.x, v2.y);
        hh[5] = __floats2half2_rn(v2.z, v2.w);
        hh[6] = __floats2half2_rn(v3.x, v3.y);
        hh[7] = __floats2half2_rn(v3.z, v3.w);
        uint4* d4 = reinterpret_cast<uint4*>(dst) + off * 2;
        d4[0] = *reinterpret_cast<uint4*>(&hh[0]);   // default .wb: stays in L2
        d4[1] = *reinterpret_cast<uint4*>(&hh[4]);
    }
}

static __device__ __forceinline__ uint32_t cvta_s(const void* p) {
    return (uint32_t)__cvta_generic_to_shared(p);
}
static __device__ __forceinline__ void cp_async16(uint32_t dst, const void* src) {
    asm volatile("cp.async.cg.shared.global [%0], [%1], 16;" :: "r"(dst), "l"(src));
}
static __device__ __forceinline__ void ldsm4(uint32_t* r, uint32_t addr) {
    asm volatile("ldmatrix.sync.aligned.m8n8.x4.shared.b16 {%0,%1,%2,%3}, [%4];"
        : "=r"(r[0]), "=r"(r[1]), "=r"(r[2]), "=r"(r[3]) : "r"(addr));
}
static __device__ __forceinline__ void mma16816(float* d, const uint32_t* a,
                                                uint32_t b0, uint32_t b1) {
    asm volatile(
        "mma.sync.aligned.m16n8k16.row.col.f32.f16.f16.f32 "
        "{%0,%1,%2,%3}, {%4,%5,%6,%7}, {%8,%9}, {%0,%1,%2,%3};"
        : "+f"(d[0]), "+f"(d[1]), "+f"(d[2]), "+f"(d[3])
        : "r"(a[0]), "r"(a[1]), "r"(a[2]), "r"(a[3]), "r"(b0), "r"(b1));
}

__global__ __launch_bounds__(256, 2) void lstm_fp16_kernel(
    const float* __restrict__ c, const float* __restrict__ bi,
    float* __restrict__ out)
{
    extern __shared__ __align__(16) char smem[];
    __half* stage0 = (__half*)smem;
    float*  bias_s = (float*)(smem + NSTAGE * STAGE_BYTES);  // 128 floats

    const int tid  = threadIdx.x;
    const int lane = tid & 31;
    const int warp = tid >> 5;
    const int h0   = blockIdx.x * 32;   // 32 h-cols (x4 gates = 128 N)
    const int row0 = blockIdx.y * 128;  // 128 batch rows

    if (tid < 128) bias_s[tid] = bi[(tid >> 5) * Hd + h0 + (tid & 31)];

    const int wm  = warp & 1;           // 2 warps along M (64 rows each)
    const int wn  = warp >> 1;          // 4 warps along N (32 cols each)
    const int M0  = wm * 64;
    const int N0w = wn * 32;

    const int blk = lane >> 3, r8 = lane & 7;
    const int lmRow = (blk & 1) * 8 + r8;
    const int lmCol = (blk >> 1) * 8;

    float acc[4][4][4] = {};

    auto prefetch = [&](int s, int slot) {
        const __half* Ap = (s < 16) ? g_xh : g_xh + 16777216;
        const __half* Wp = (s < 16) ? g_ww : g_ww + 4194304;
        const int kl = (s & 15) * BKH;
        const uint32_t sa = cvta_s(stage0 + (size_t)slot * STAGE_H);
        const uint32_t sb = sa + A_STAGE_H * 2;
        #pragma unroll
        for (int it = 0; it < 4; it++) {           // A: 1024 x 16B chunks
            int ci = tid + it * 256;
            int row = ci >> 3, j = ci & 7;
            cp_async16(sa + (uint32_t)(row * SROW + j * 8) * 2u,
                       Ap + (size_t)(row0 + row) * 1024 + kl + j * 8);
        }
        #pragma unroll
        for (int it = 0; it < 4; it++) {           // B: 1024 x 16B chunks
            int ci = tid + it * 256;
            int cc = ci >> 3, j = ci & 7;
            int wrow = (cc >> 5) * 1024 + h0 + (cc & 31);
            cp_async16(sb + (uint32_t)(cc * SROW + j * 8) * 2u,
                       Wp + (size_t)wrow * 1024 + kl + j * 8);
        }
        asm volatile("cp.async.commit_group;");
    };

    prefetch(0, 0);
    prefetch(1, 1);

    // hoisted per-slot fragment base addresses (removes per-stage IMAD chain)
    uint32_t aBs[NSTAGE], bBs[NSTAGE];
    #pragma unroll
    for (int sl = 0; sl < NSTAGE; sl++) {
        uint32_t sa = cvta_s(stage0 + (size_t)sl * STAGE_H);
        aBs[sl] = sa + (uint32_t)((M0 + lmRow) * SROW + lmCol) * 2u;
        bBs[sl] = sa + A_STAGE_H * 2 + (uint32_t)((N0w + lmRow) * SROW + lmCol) * 2u;
    }

    int slot = 0;
    for (int s = 0; s < 32; s++) {
        asm volatile("cp.async.wait_group 1;" ::: "memory");   // stage s arrived
        __syncthreads();   // readers of slot (s-1)%3 done; stage s data visible

        if (s + 2 < 32) prefetch(s + 2, (s + 2) % 3);          // into freed slot
        else asm volatile("cp.async.commit_group;");           // keep group count

        const uint32_t aB = aBs[slot];
        const uint32_t bB = bBs[slot];
        if (++slot == NSTAGE) slot = 0;

        #pragma unroll
        for (int ks = 0; ks < 4; ks++) {           // four k16 steps per stage
            const uint32_t ko = (uint32_t)(ks * 16) * 2u;
            uint32_t a[4][4];
            #pragma unroll
            for (int i = 0; i < 4; i++)
                ldsm4(a[i], aB + (uint32_t)(i * 16 * SROW) * 2u + ko);
            uint32_t bf[2][4];
            ldsm4(bf[0], bB + ko);
            ldsm4(bf[1], bB + (uint32_t)(16 * SROW) * 2u + ko);

            #pragma unroll
            for (int i = 0; i < 4; i++)
                #pragma unroll
                for (int j = 0; j < 4; j++)
                    mma16816(acc[i][j], a[i],
                             bf[j >> 1][j & 1], bf[j >> 1][2 + (j & 1)]);
        }
    }
    __syncthreads();

    // ---- fused LSTM epilogue: 2 passes of 64-row smem transpose ----
    float* Ps = (float*)smem;            // [64][132] floats = 33792 B
    const size_t BH = (size_t)Bsz * Hd;
    const int fr = lane >> 2, fc = lane & 3;

    #pragma unroll
    for (int p = 0; p < 2; p++) {
        if (wm == p) {
            #pragma unroll
            for (int i = 0; i < 4; i++)
                #pragma unroll
                for (int j = 0; j < 4; j++) {
                    int rr = i * 16 + fr;
                    int cc = N0w + j * 8 + 2 * fc;
                    Ps[rr * 132 + cc]           = acc[i][j][0];
                    Ps[rr * 132 + cc + 1]       = acc[i][j][1];
                    Ps[(rr + 8) * 132 + cc]     = acc[i][j][2];
                    Ps[(rr + 8) * 132 + cc + 1] = acc[i][j][3];
                }
        }
        __syncthreads();

        const int rloc = tid >> 2;            // 0..63
        const int hh0  = (tid & 3) * 8;       // 8 h-cols per thread
        const int bg   = row0 + p * 64 + rloc;
        const size_t idx0 = (size_t)bg * Hd + h0 + hh0;
        #pragma unroll
        for (int q4 = 0; q4 < 2; q4++) {
            float4 cv = *reinterpret_cast<const float4*>(c + idx0 + q4 * 4);
            float cvv[4] = {cv.x, cv.y, cv.z, cv.w};
            float o4[4], nh4[4], nc4[4];
            #pragma unroll
            for (int e = 0; e < 4; e++) {
                int hh = hh0 + q4 * 4 + e;
                float iv = Ps[rloc * 132 + hh]      + bias_s[hh];
                float fv = Ps[rloc * 132 + 32 + hh] + bias_s[32 + hh];
                float gv = Ps[rloc * 132 + 64 + hh] + bias_s[64 + hh];
                float ov = Ps[rloc * 132 + 96 + hh] + bias_s[96 + hh];
                float is = 1.f / (1.f + __expf(-iv));
                float fs = 1.f / (1.f + __expf(-fv));
                float gt = tanhf(gv);
                float os = 1.f / (1.f + __expf(-ov));
                float nc = fs * cvv[e] + is * gt;
                float nh = os * tanhf(nc);
                o4[e] = os; nh4[e] = nh; nc4[e] = nc;
            }
            *reinterpret_cast<float4*>(out + idx0 + q4 * 4) =
                make_float4(o4[0], o4[1], o4[2], o4[3]);
            *reinterpret_cast<float4*>(out + BH + idx0 + q4 * 4) =
                make_float4(nh4[0], nh4[1], nh4[2], nh4[3]);
            *reinterpret_cast<float4*>(out + 2 * BH + idx0 + q4 * 4) =
                make_float4(nc4[0], nc4[1], nc4[2], nc4[3]);
        }
        __syncthreads();
    }
}

extern "C" void kernel_launch(void* const* d_in, const int* in_sizes, int n_in,
                              void* d_out, int out_size) {
    const float* x  = (const float*)d_in[0];
    const float* h  = (const float*)d_in[1];
    const float* c  = (const float*)d_in[2];
    const float* Wi = (const float*)d_in[3];
    const float* bi = (const float*)d_in[4];
    const float* Wh = (const float*)d_in[5];
    float* out = (float*)d_out;

    cvt_all_kernel<<<4096, 512>>>(x, h, Wi, Wh);   // 40M floats

    const int smem_bytes = NSTAGE * STAGE_BYTES + 512 + 256;   // ~111.4 KB/CTA
    static int configured = -1;
    if (configured < 0) {
        cudaFuncSetAttribute(lstm_fp16_kernel,
                             cudaFuncAttributeMaxDynamicSharedMemorySize, smem_bytes);
        configured = 1;
    }
    dim3 grid(Hd / 32, Bsz / 128);   // (32, 128) = 4096 CTAs
    lstm_fp16_kernel<<<grid, 256, smem_bytes>>>(c, bi, out);
}

// round 17
// speedup vs baseline: 1.0100x; 1.0100x over previous
#include <cuda_runtime.h>
#include <cuda_fp16.h>
#include <math.h>
#include <stdint.h>

// LSTMCell fused, fp16 mma.sync.m16n8k16 f32-accum (sm_103 — no tcgen05 in toolchain).
// Main GEMM kernel at the legacy-HMMA issue wall (~877us = 67.1M HMMA at ~16
// cyc/SMSP issue cadence). Config = best measured (R15): CTA 128x128 (4 gates x
// 32 h), 256 threads, 8 warps (2M x 4N), warp tile 64x32, K=2048 in 32 stages
// of 64 halves, 3-slot cp.async pipeline, 2 CTAs/SM, streaming cvt pre-pass.
// Epilogue micro-opt: c loads issued before Ps reads to overlap DRAM latency.

#define Bsz 16384
#define Hd  1024
#define BKH 64                     // halves per K stage
#define SROW 72                    // 64 + 8 pad halves (144B rows, LDSM conflict-free)
#define A_STAGE_H (128 * SROW)     // 9216 halves
#define B_STAGE_H (128 * SROW)     // 9216 halves
#define STAGE_H   (A_STAGE_H + B_STAGE_H)
#define STAGE_BYTES (STAGE_H * 2)  // 36864 B
#define NSTAGE 3

__device__ __half g_xh[33554432];  // x | h   (2 x 16M)
__device__ __half g_ww[8388608];   // Wi | Wh (2 x 4M)

// Streaming conversion: 40M floats, 16 per thread-iteration, grid-stride;
// ld.global.cs / st.global.cs (exact R15 configuration).
__global__ __launch_bounds__(512) void cvt_all_kernel(
    const float* __restrict__ x,  const float* __restrict__ h,
    const float* __restrict__ Wi, const float* __restrict__ Wh)
{
    const int nthreads = gridDim.x * blockDim.x;
    for (int i = blockIdx.x * blockDim.x + threadIdx.x; i < 2621440; i += nthreads) {
        const float* src; __half* dst; int off;   // off in 16-float units
        if (i < 1048576)      { src = x;  dst = g_xh;            off = i; }
        else if (i < 2097152) { src = h;  dst = g_xh + 16777216; off = i - 1048576; }
        else if (i < 2359296) { src = Wi; dst = g_ww;            off = i - 2097152; }
        else                  { src = Wh; dst = g_ww + 4194304;  off = i - 2359296; }
        const float4* s4 = reinterpret_cast<const float4*>(src) + off * 4;
        float4 v0 = __ldcs(s4);
        float4 v1 = __ldcs(s4 + 1);
        float4 v2 = __ldcs(s4 + 2);
        float4 v3 = __ldcs(s4 + 3);
        __half2 hh[8];
        hh[0] = __floats2half2_rn(v0.x, v0.y);
        hh[1] = __floats2half2_rn(v0.z, v0.w);
        hh[2] = __floats2half2_rn(v1.x, v1.y);
        hh[3] = __floats2half2_rn(v1.z, v1.w);
        hh[4] = __floats2half2_rn(v2.x, v2.y);
        hh[5] = __floats2half2_rn(v2.z, v2.w);
        hh[6] = __floats2half2_rn(v3.x, v3.y);
        hh[7] = __floats2half2_rn(v3.z, v3.w);
        uint4* d4 = reinterpret_cast<uint4*>(dst) + off * 2;
        __stcs(d4,     *reinterpret_cast<uint4*>(&hh[0]));
        __stcs(d4 + 1, *reinterpret_cast<uint4*>(&hh[4]));
    }
}

static __device__ __forceinline__ uint32_t cvta_s(const void* p) {
    return (uint32_t)__cvta_generic_to_shared(p);
}
static __device__ __forceinline__ void cp_async16(uint32_t dst, const void* src) {
    asm volatile("cp.async.cg.shared.global [%0], [%1], 16;" :: "r"(dst), "l"(src));
}
static __device__ __forceinline__ void ldsm4(uint32_t* r, uint32_t addr) {
    asm volatile("ldmatrix.sync.aligned.m8n8.x4.shared.b16 {%0,%1,%2,%3}, [%4];"
        : "=r"(r[0]), "=r"(r[1]), "=r"(r[2]), "=r"(r[3]) : "r"(addr));
}
static __device__ __forceinline__ void mma16816(float* d, const uint32_t* a,
                                                uint32_t b0, uint32_t b1) {
    asm volatile(
        "mma.sync.aligned.m16n8k16.row.col.f32.f16.f16.f32 "
        "{%0,%1,%2,%3}, {%4,%5,%6,%7}, {%8,%9}, {%0,%1,%2,%3};"
        : "+f"(d[0]), "+f"(d[1]), "+f"(d[2]), "+f"(d[3])
        : "r"(a[0]), "r"(a[1]), "r"(a[2]), "r"(a[3]), "r"(b0), "r"(b1));
}

__global__ __launch_bounds__(256, 2) void lstm_fp16_kernel(
    const float* __restrict__ c, const float* __restrict__ bi,
    float* __restrict__ out)
{
    extern __shared__ __align__(16) char smem[];
    __half* stage0 = (__half*)smem;
    float*  bias_s = (float*)(smem + NSTAGE * STAGE_BYTES);  // 128 floats

    const int tid  = threadIdx.x;
    const int lane = tid & 31;
    const int warp = tid >> 5;
    const int h0   = blockIdx.x * 32;   // 32 h-cols (x4 gates = 128 N)
    const int row0 = blockIdx.y * 128;  // 128 batch rows

    if (tid < 128) bias_s[tid] = bi[(tid >> 5) * Hd + h0 + (tid & 31)];

    const int wm  = warp & 1;           // 2 warps along M (64 rows each)
    const int wn  = warp >> 1;          // 4 warps along N (32 cols each)
    const int M0  = wm * 64;
    const int N0w = wn * 32;

    const int blk = lane >> 3, r8 = lane & 7;
    const int lmRow = (blk & 1) * 8 + r8;
    const int lmCol = (blk >> 1) * 8;

    float acc[4][4][4] = {};

    auto prefetch = [&](int s, int slot) {
        const __half* Ap = (s < 16) ? g_xh : g_xh + 16777216;
        const __half* Wp = (s < 16) ? g_ww : g_ww + 4194304;
        const int kl = (s & 15) * BKH;
        const uint32_t sa = cvta_s(stage0 + (size_t)slot * STAGE_H);
        const uint32_t sb = sa + A_STAGE_H * 2;
        #pragma unroll
        for (int it = 0; it < 4; it++) {           // A: 1024 x 16B chunks
            int ci = tid + it * 256;
            int row = ci >> 3, j = ci & 7;
            cp_async16(sa + (uint32_t)(row * SROW + j * 8) * 2u,
                       Ap + (size_t)(row0 + row) * 1024 + kl + j * 8);
        }
        #pragma unroll
        for (int it = 0; it < 4; it++) {           // B: 1024 x 16B chunks
            int ci = tid + it * 256;
            int cc = ci >> 3, j = ci & 7;
            int wrow = (cc >> 5) * 1024 + h0 + (cc & 31);
            cp_async16(sb + (uint32_t)(cc * SROW + j * 8) * 2u,
                       Wp + (size_t)wrow * 1024 + kl + j * 8);
        }
        asm volatile("cp.async.commit_group;");
    };

    prefetch(0, 0);
    prefetch(1, 1);

    for (int s = 0; s < 32; s++) {
        asm volatile("cp.async.wait_group 1;" ::: "memory");   // stage s arrived
        __syncthreads();   // readers of slot (s-1)%3 done; stage s data visible

        if (s + 2 < 32) prefetch(s + 2, (s + 2) % 3);          // into freed slot
        else asm volatile("cp.async.commit_group;");           // keep group count

        const uint32_t sa = cvta_s(stage0 + (size_t)(s % 3) * STAGE_H);
        const uint32_t sb = sa + A_STAGE_H * 2;
        const uint32_t aB = sa + (uint32_t)((M0 + lmRow) * SROW + lmCol) * 2u;
        const uint32_t bB = sb + (uint32_t)((N0w + lmRow) * SROW + lmCol) * 2u;

        #pragma unroll
        for (int ks = 0; ks < 4; ks++) {           // four k16 steps per stage
            const uint32_t ko = (uint32_t)(ks * 16) * 2u;
            uint32_t a[4][4];
            #pragma unroll
            for (int i = 0; i < 4; i++)
                ldsm4(a[i], aB + (uint32_t)(i * 16 * SROW) * 2u + ko);
            uint32_t bf[2][4];
            ldsm4(bf[0], bB + ko);
            ldsm4(bf[1], bB + (uint32_t)(16 * SROW) * 2u + ko);

            #pragma unroll
            for (int i = 0; i < 4; i++)
                #pragma unroll
                for (int j = 0; j < 4; j++)
                    mma16816(acc[i][j], a[i],
                             bf[j >> 1][j & 1], bf[j >> 1][2 + (j & 1)]);
        }
    }
    __syncthreads();

    // ---- fused LSTM epilogue: 2 passes of 64-row smem transpose ----
    float* Ps = (float*)smem;            // [64][132] floats = 33792 B
    const size_t BH = (size_t)Bsz * Hd;
    const int fr = lane >> 2, fc = lane & 3;

    #pragma unroll
    for (int p = 0; p < 2; p++) {
        if (wm == p) {
            #pragma unroll
            for (int i = 0; i < 4; i++)
                #pragma unroll
                for (int j = 0; j < 4; j++) {
                    int rr = i * 16 + fr;
                    int cc = N0w + j * 8 + 2 * fc;
                    Ps[rr * 132 + cc]           = acc[i][j][0];
                    Ps[rr * 132 + cc + 1]       = acc[i][j][1];
                    Ps[(rr + 8) * 132 + cc]     = acc[i][j][2];
                    Ps[(rr + 8) * 132 + cc + 1] = acc[i][j][3];
                }
        }
        __syncthreads();

        const int rloc = tid >> 2;            // 0..63
        const int hh0  = (tid & 3) * 8;       // 8 h-cols per thread
        const int bg   = row0 + p * 64 + rloc;
        const size_t idx0 = (size_t)bg * Hd + h0 + hh0;

        // issue both c loads FIRST so DRAM latency overlaps the Ps/bias reads
        float4 cva = *reinterpret_cast<const float4*>(c + idx0);
        float4 cvb = *reinterpret_cast<const float4*>(c + idx0 + 4);

        #pragma unroll
        for (int q4 = 0; q4 < 2; q4++) {
            float cvv[4];
            if (q4 == 0) { cvv[0]=cva.x; cvv[1]=cva.y; cvv[2]=cva.z; cvv[3]=cva.w; }
            else         { cvv[0]=cvb.x; cvv[1]=cvb.y; cvv[2]=cvb.z; cvv[3]=cvb.w; }
            float o4[4], nh4[4], nc4[4];
            #pragma unroll
            for (int e = 0; e < 4; e++) {
                int hh = hh0 + q4 * 4 + e;
                float iv = Ps[rloc * 132 + hh]      + bias_s[hh];
                float fv = Ps[rloc * 132 + 32 + hh] + bias_s[32 + hh];
                float gv = Ps[rloc * 132 + 64 + hh] + bias_s[64 + hh];
                float ov = Ps[rloc * 132 + 96 + hh] + bias_s[96 + hh];
                float is = 1.f / (1.f + __expf(-iv));
                float fs = 1.f / (1.f + __expf(-fv));
                float gt = tanhf(gv);
                float os = 1.f / (1.f + __expf(-ov));
                float nc = fs * cvv[e] + is * gt;
                float nh = os * tanhf(nc);
                o4[e] = os; nh4[e] = nh; nc4[e] = nc;
            }
            *reinterpret_cast<float4*>(out + idx0 + q4 * 4) =
                make_float4(o4[0], o4[1], o4[2], o4[3]);
            *reinterpret_cast<float4*>(out + BH + idx0 + q4 * 4) =
                make_float4(nh4[0], nh4[1], nh4[2], nh4[3]);
            *reinterpret_cast<float4*>(out + 2 * BH + idx0 + q4 * 4) =
                make_float4(nc4[0], nc4[1], nc4[2], nc4[3]);
        }
        __syncthreads();
    }
}

extern "C" void kernel_launch(void* const* d_in, const int* in_sizes, int n_in,
                              void* d_out, int out_size) {
    const float* x  = (const float*)d_in[0];
    const float* h  = (const float*)d_in[1];
    const float* c  = (const float*)d_in[2];
    const float* Wi = (const float*)d_in[3];
    const float* bi = (const float*)d_in[4];
    const float* Wh = (const float*)d_in[5];
    float* out = (float*)d_out;

    cvt_all_kernel<<<2560, 512>>>(x, h, Wi, Wh);   // 40M floats, 16/thread/iter

    const int smem_bytes = NSTAGE * STAGE_BYTES + 512 + 256;   // ~111.4 KB/CTA
    static int configured = -1;
    if (configured < 0) {
        cudaFuncSetAttribute(lstm_fp16_kernel,
                             cudaFuncAttributeMaxDynamicSharedMemorySize, smem_bytes);
        configured = 1;
    }
    dim3 grid(Hd / 32, Bsz / 128);   // (32, 128) = 4096 CTAs
    lstm_fp16_kernel<<<grid, 256, smem_bytes>>>(c, bi, out);
}